// round 2
// baseline (speedup 1.0000x reference)
#include <cuda_runtime.h>
#include <cuda_bf16.h>
#include <cstddef>

// Problem constants
#define T_DIM 2048
#define B_DIM 2
#define E_DIM 1024
#define H_DIM 16
#define HD_DIM 64
#define E3_DIM 3072
#define NROWS (T_DIM * B_DIM)   // 4096

// Scratch (device globals: allocation-free rule)
__device__ float g_ln[(size_t)NROWS * E_DIM];    // 16 MB
__device__ float g_qkv[(size_t)NROWS * E3_DIM];  // 48 MB
__device__ float g_ctx[(size_t)NROWS * E_DIM];   // 16 MB

// ---------------------------------------------------------------------------
// LayerNorm: one block per (t,b) row of 1024
// ---------------------------------------------------------------------------
__global__ void ln_kernel(const float* __restrict__ x,
                          const float* __restrict__ gamma,
                          const float* __restrict__ beta,
                          float* __restrict__ y) {
    __shared__ float red_s[8], red_q[8];
    int row = blockIdx.x;
    int t = threadIdx.x;
    const float4* xr = (const float4*)(x + (size_t)row * E_DIM);
    float4 v = xr[t];
    float s = v.x + v.y + v.z + v.w;
    float q = v.x * v.x + v.y * v.y + v.z * v.z + v.w * v.w;
#pragma unroll
    for (int o = 16; o; o >>= 1) {
        s += __shfl_xor_sync(0xffffffffu, s, o);
        q += __shfl_xor_sync(0xffffffffu, q, o);
    }
    if ((t & 31) == 0) { red_s[t >> 5] = s; red_q[t >> 5] = q; }
    __syncthreads();
    if (t < 32) {
        s = (t < 8) ? red_s[t] : 0.f;
        q = (t < 8) ? red_q[t] : 0.f;
#pragma unroll
        for (int o = 4; o; o >>= 1) {
            s += __shfl_xor_sync(0xffffffffu, s, o);
            q += __shfl_xor_sync(0xffffffffu, q, o);
        }
        if (t == 0) { red_s[0] = s; red_q[0] = q; }
    }
    __syncthreads();
    s = red_s[0]; q = red_q[0];
    float mean = s * (1.0f / E_DIM);
    float var = q * (1.0f / E_DIM) - mean * mean;
    float inv = rsqrtf(var + 1e-5f);
    float4 g = ((const float4*)gamma)[t];
    float4 bb = ((const float4*)beta)[t];
    float4 o4;
    o4.x = (v.x - mean) * inv * g.x + bb.x;
    o4.y = (v.y - mean) * inv * g.y + bb.y;
    o4.z = (v.z - mean) * inv * g.z + bb.z;
    o4.w = (v.w - mean) * inv * g.w + bb.w;
    ((float4*)(y + (size_t)row * E_DIM))[t] = o4;
}

// ---------------------------------------------------------------------------
// SGEMM: C[M,N] = A[M,K] * B[N,K]^T (+ residual). 128x128 tile, KT=8,
// 256 threads, 8x8 micro-tile, float4 fragments.
// M,N,K all multiples of 128 here; no bounds checks.
// ---------------------------------------------------------------------------
__global__ void __launch_bounds__(256) gemm_tn128(
    const float* __restrict__ A, const float* __restrict__ Bw,
    float* __restrict__ C, const float* __restrict__ res,
    int M, int N, int K) {
    __shared__ float As[8][128];
    __shared__ float Bs[8][128];
    int t = threadIdx.x;
    int tx = t & 15, ty = t >> 4;
    int m0 = blockIdx.y * 128, n0 = blockIdx.x * 128;

    int lrow = t >> 1;           // 0..127
    int lk4 = (t & 1) * 4;       // 0 or 4
    const float* Ag = A + (size_t)(m0 + lrow) * K + lk4;
    const float* Bg = Bw + (size_t)(n0 + lrow) * K + lk4;

    float acc[8][8];
#pragma unroll
    for (int j = 0; j < 8; j++)
#pragma unroll
        for (int i = 0; i < 8; i++) acc[j][i] = 0.f;

    for (int k0 = 0; k0 < K; k0 += 8) {
        float4 av = *(const float4*)(Ag + k0);
        float4 bv = *(const float4*)(Bg + k0);
        __syncthreads();
        As[lk4 + 0][lrow] = av.x; As[lk4 + 1][lrow] = av.y;
        As[lk4 + 2][lrow] = av.z; As[lk4 + 3][lrow] = av.w;
        Bs[lk4 + 0][lrow] = bv.x; Bs[lk4 + 1][lrow] = bv.y;
        Bs[lk4 + 2][lrow] = bv.z; Bs[lk4 + 3][lrow] = bv.w;
        __syncthreads();
#pragma unroll
        for (int kk = 0; kk < 8; kk++) {
            float4 a0 = *(const float4*)&As[kk][ty * 8];
            float4 a1 = *(const float4*)&As[kk][ty * 8 + 4];
            float4 b0 = *(const float4*)&Bs[kk][tx * 8];
            float4 b1 = *(const float4*)&Bs[kk][tx * 8 + 4];
            float a[8] = {a0.x, a0.y, a0.z, a0.w, a1.x, a1.y, a1.z, a1.w};
            float b[8] = {b0.x, b0.y, b0.z, b0.w, b1.x, b1.y, b1.z, b1.w};
#pragma unroll
            for (int j = 0; j < 8; j++)
#pragma unroll
                for (int i = 0; i < 8; i++) acc[j][i] += a[j] * b[i];
        }
    }

#pragma unroll
    for (int j = 0; j < 8; j++) {
        size_t row = (size_t)(m0 + ty * 8 + j);
        float* crow = C + row * N + n0 + tx * 8;
        float4 v0 = make_float4(acc[j][0], acc[j][1], acc[j][2], acc[j][3]);
        float4 v1 = make_float4(acc[j][4], acc[j][5], acc[j][6], acc[j][7]);
        if (res) {
            const float* rrow = res + row * N + n0 + tx * 8;
            float4 r0v = *(const float4*)(rrow);
            float4 r1v = *(const float4*)(rrow + 4);
            v0.x += r0v.x; v0.y += r0v.y; v0.z += r0v.z; v0.w += r0v.w;
            v1.x += r1v.x; v1.y += r1v.y; v1.z += r1v.z; v1.w += r1v.w;
        }
        *(float4*)(crow) = v0;
        *(float4*)(crow + 4) = v1;
    }
}

// ---------------------------------------------------------------------------
// Flash-style attention. One block = 64 query rows for one (b,h).
// 256 threads (16x16), 4x4 micro-tiles, online softmax.
// Shared: Qs[64][65], KPs[64][65] (K tile, reused for P), Vs[64][64].
// Vs needs no pad: per-thread 4-float chunks across tx, broadcast across ty.
// ---------------------------------------------------------------------------
#define ATT_STRIDE 65
#define ATT_VOFF   (2 * 64 * ATT_STRIDE)
#define ATT_SMEM_BYTES ((2 * 64 * ATT_STRIDE + 64 * 64) * 4)

__global__ void __launch_bounds__(256) attn_kernel(
    const float* __restrict__ qkv, float* __restrict__ ctx) {
    extern __shared__ float sm[];
    float* Qs = sm;
    float* KPs = sm + 64 * ATT_STRIDE;
    float* Vs = sm + ATT_VOFF;

    int qt = blockIdx.x;
    int bh = blockIdx.y;
    int b = bh >> 4, h = bh & 15;
    int tid = threadIdx.x;
    int tx = tid & 15, ty = tid >> 4;
    int r0 = ty * 4, c0 = tx * 4;

    // Load Q tile (scaled by HD^-0.5 = 0.125)
#pragma unroll
    for (int i = 0; i < 16; i++) {
        int e = tid + i * 256;
        int r = e >> 6, d = e & 63;
        size_t g = ((size_t)(qt * 64 + r) * B_DIM + b) * E3_DIM + h * 64 + d;
        Qs[r * ATT_STRIDE + d] = qkv[g] * 0.125f;
    }

    float m[4], l[4], o[4][4];
#pragma unroll
    for (int j = 0; j < 4; j++) {
        m[j] = -1e30f; l[j] = 0.f;
#pragma unroll
        for (int i = 0; i < 4; i++) o[j][i] = 0.f;
    }

    for (int kt = 0; kt < T_DIM / 64; kt++) {
        __syncthreads();  // prev-iter P/V reads done; also covers Q store on first iter
#pragma unroll
        for (int i = 0; i < 16; i++) {
            int e = tid + i * 256;
            int c = e >> 6, d = e & 63;
            size_t gk = ((size_t)(kt * 64 + c) * B_DIM + b) * E3_DIM + E_DIM + h * 64 + d;
            KPs[c * ATT_STRIDE + d] = qkv[gk];
            Vs[c * 64 + d] = qkv[gk + E_DIM];
        }
        __syncthreads();

        // S = Q K^T (64x64 tile), 4x4 per thread
        float s[4][4];
#pragma unroll
        for (int j = 0; j < 4; j++)
#pragma unroll
            for (int i = 0; i < 4; i++) s[j][i] = 0.f;
        for (int d = 0; d < 64; d++) {
            float aq[4], bk[4];
#pragma unroll
            for (int j = 0; j < 4; j++) aq[j] = Qs[(r0 + j) * ATT_STRIDE + d];
#pragma unroll
            for (int i = 0; i < 4; i++) bk[i] = KPs[(c0 + i) * ATT_STRIDE + d];
#pragma unroll
            for (int j = 0; j < 4; j++)
#pragma unroll
                for (int i = 0; i < 4; i++) s[j][i] += aq[j] * bk[i];
        }

        // Row max across the 16 tx-threads
        float mnew[4], p[4][4], rs[4];
#pragma unroll
        for (int j = 0; j < 4; j++) {
            float rm = fmaxf(fmaxf(s[j][0], s[j][1]), fmaxf(s[j][2], s[j][3]));
#pragma unroll
            for (int off = 8; off; off >>= 1)
                rm = fmaxf(rm, __shfl_xor_sync(0xffffffffu, rm, off));
            mnew[j] = fmaxf(m[j], rm);
        }
#pragma unroll
        for (int j = 0; j < 4; j++) {
            float sum = 0.f;
#pragma unroll
            for (int i = 0; i < 4; i++) {
                p[j][i] = __expf(s[j][i] - mnew[j]);
                sum += p[j][i];
            }
#pragma unroll
            for (int off = 8; off; off >>= 1)
                sum += __shfl_xor_sync(0xffffffffu, sum, off);
            rs[j] = sum;
        }

        __syncthreads();  // everyone done reading K from KPs
#pragma unroll
        for (int j = 0; j < 4; j++)
#pragma unroll
            for (int i = 0; i < 4; i++)
                KPs[(r0 + j) * ATT_STRIDE + c0 + i] = p[j][i];
        __syncthreads();

#pragma unroll
        for (int j = 0; j < 4; j++) {
            float sc = __expf(m[j] - mnew[j]);
            l[j] = l[j] * sc + rs[j];
            m[j] = mnew[j];
#pragma unroll
            for (int i = 0; i < 4; i++) o[j][i] *= sc;
        }

        // O += P @ V  (output cols = HD dims, same 4x4 indexing)
        for (int c = 0; c < 64; c++) {
            float pj[4], vi[4];
#pragma unroll
            for (int j = 0; j < 4; j++) pj[j] = KPs[(r0 + j) * ATT_STRIDE + c];
#pragma unroll
            for (int i = 0; i < 4; i++) vi[i] = Vs[c * 64 + c0 + i];
#pragma unroll
            for (int j = 0; j < 4; j++)
#pragma unroll
                for (int i = 0; i < 4; i++) o[j][i] += pj[j] * vi[i];
        }
    }

#pragma unroll
    for (int j = 0; j < 4; j++) {
        float linv = 1.0f / l[j];
#pragma unroll
        for (int i = 0; i < 4; i++) {
            size_t g = ((size_t)(qt * 64 + r0 + j) * B_DIM + b) * E_DIM + h * 64 + c0 + i;
            ctx[g] = o[j][i] * linv;
        }
    }
}

// ---------------------------------------------------------------------------
extern "C" void kernel_launch(void* const* d_in, const int* in_sizes, int n_in,
                              void* d_out, int out_size) {
    const float* query = (const float*)d_in[0];
    const float* gamma = (const float*)d_in[1];
    const float* beta  = (const float*)d_in[2];
    const float* w_in  = (const float*)d_in[3];
    const float* w_out = (const float*)d_in[4];
    float* out = (float*)d_out;

    float *ln_p, *qkv_p, *ctx_p;
    cudaGetSymbolAddress((void**)&ln_p, g_ln);
    cudaGetSymbolAddress((void**)&qkv_p, g_qkv);
    cudaGetSymbolAddress((void**)&ctx_p, g_ctx);

    cudaFuncSetAttribute(attn_kernel, cudaFuncAttributeMaxDynamicSharedMemorySize,
                         ATT_SMEM_BYTES);

    // 1. LayerNorm
    ln_kernel<<<NROWS, 256>>>(query, gamma, beta, ln_p);

    // 2. QKV projection: [4096,1024] x [3072,1024]^T
    gemm_tn128<<<dim3(E3_DIM / 128, NROWS / 128), 256>>>(
        ln_p, w_in, qkv_p, nullptr, NROWS, E3_DIM, E_DIM);

    // 3. Attention
    attn_kernel<<<dim3(T_DIM / 64, B_DIM * H_DIM), 256, ATT_SMEM_BYTES>>>(
        qkv_p, ctx_p);

    // 4. Output projection + residual
    gemm_tn128<<<dim3(E_DIM / 128, NROWS / 128), 256>>>(
        ctx_p, w_out, out, query, NROWS, E_DIM, E_DIM);
}

// round 4
// speedup vs baseline: 1.2609x; 1.2609x over previous
#include <cuda_runtime.h>
#include <cuda_bf16.h>
#include <cstddef>
#include <cstdint>

// Problem constants
#define T_DIM 2048
#define B_DIM 2
#define E_DIM 1024
#define H_DIM 16
#define HD_DIM 64
#define E3_DIM 3072
#define NROWS (T_DIM * B_DIM)   // 4096

// Scratch (device globals: allocation-free rule)
__device__ float g_ln[(size_t)NROWS * E_DIM];    // 16 MB
__device__ float g_qkv[(size_t)NROWS * E3_DIM];  // 48 MB
__device__ float g_ctx[(size_t)NROWS * E_DIM];   // 16 MB

// ---------------------------------------------------------------------------
// Helpers: tf32 convert + m16n8k8 tf32 mma
// ---------------------------------------------------------------------------
__device__ __forceinline__ uint32_t f2tf(float x) {
    uint32_t r;
    asm("cvt.rna.tf32.f32 %0, %1;" : "=r"(r) : "f"(x));
    return r;
}

__device__ __forceinline__ void mma_tf32(float* d, const uint32_t* a,
                                         uint32_t b0, uint32_t b1) {
    asm volatile(
        "mma.sync.aligned.m16n8k8.row.col.f32.tf32.tf32.f32 "
        "{%0,%1,%2,%3}, {%4,%5,%6,%7}, {%8,%9}, {%0,%1,%2,%3};"
        : "+f"(d[0]), "+f"(d[1]), "+f"(d[2]), "+f"(d[3])
        : "r"(a[0]), "r"(a[1]), "r"(a[2]), "r"(a[3]), "r"(b0), "r"(b1));
}

// ---------------------------------------------------------------------------
// LayerNorm: one block per (t,b) row of 1024
// ---------------------------------------------------------------------------
__global__ void ln_kernel(const float* __restrict__ x,
                          const float* __restrict__ gamma,
                          const float* __restrict__ beta,
                          float* __restrict__ y) {
    __shared__ float red_s[8], red_q[8];
    int row = blockIdx.x;
    int t = threadIdx.x;
    const float4* xr = (const float4*)(x + (size_t)row * E_DIM);
    float4 v = xr[t];
    float s = v.x + v.y + v.z + v.w;
    float q = v.x * v.x + v.y * v.y + v.z * v.z + v.w * v.w;
#pragma unroll
    for (int o = 16; o; o >>= 1) {
        s += __shfl_xor_sync(0xffffffffu, s, o);
        q += __shfl_xor_sync(0xffffffffu, q, o);
    }
    if ((t & 31) == 0) { red_s[t >> 5] = s; red_q[t >> 5] = q; }
    __syncthreads();
    if (t < 32) {
        s = (t < 8) ? red_s[t] : 0.f;
        q = (t < 8) ? red_q[t] : 0.f;
#pragma unroll
        for (int o = 4; o; o >>= 1) {
            s += __shfl_xor_sync(0xffffffffu, s, o);
            q += __shfl_xor_sync(0xffffffffu, q, o);
        }
        if (t == 0) { red_s[0] = s; red_q[0] = q; }
    }
    __syncthreads();
    s = red_s[0]; q = red_q[0];
    float mean = s * (1.0f / E_DIM);
    float var = q * (1.0f / E_DIM) - mean * mean;
    float inv = rsqrtf(var + 1e-5f);
    float4 g = ((const float4*)gamma)[t];
    float4 bb = ((const float4*)beta)[t];
    float4 o4;
    o4.x = (v.x - mean) * inv * g.x + bb.x;
    o4.y = (v.y - mean) * inv * g.y + bb.y;
    o4.z = (v.z - mean) * inv * g.z + bb.z;
    o4.w = (v.w - mean) * inv * g.w + bb.w;
    ((float4*)(y + (size_t)row * E_DIM))[t] = o4;
}

// ---------------------------------------------------------------------------
// SGEMM: C[M,N] = A[M,K] * B[N,K]^T (+ residual). 128x128 tile, KT=8,
// 256 threads, 8x8 micro-tile, float4 fragments. (unchanged, known-good)
// ---------------------------------------------------------------------------
__global__ void __launch_bounds__(256) gemm_tn128(
    const float* __restrict__ A, const float* __restrict__ Bw,
    float* __restrict__ C, const float* __restrict__ res,
    int M, int N, int K) {
    __shared__ float As[8][128];
    __shared__ float Bs[8][128];
    int t = threadIdx.x;
    int tx = t & 15, ty = t >> 4;
    int m0 = blockIdx.y * 128, n0 = blockIdx.x * 128;

    int lrow = t >> 1;           // 0..127
    int lk4 = (t & 1) * 4;       // 0 or 4
    const float* Ag = A + (size_t)(m0 + lrow) * K + lk4;
    const float* Bg = Bw + (size_t)(n0 + lrow) * K + lk4;

    float acc[8][8];
#pragma unroll
    for (int j = 0; j < 8; j++)
#pragma unroll
        for (int i = 0; i < 8; i++) acc[j][i] = 0.f;

    for (int k0 = 0; k0 < K; k0 += 8) {
        float4 av = *(const float4*)(Ag + k0);
        float4 bv = *(const float4*)(Bg + k0);
        __syncthreads();
        As[lk4 + 0][lrow] = av.x; As[lk4 + 1][lrow] = av.y;
        As[lk4 + 2][lrow] = av.z; As[lk4 + 3][lrow] = av.w;
        Bs[lk4 + 0][lrow] = bv.x; Bs[lk4 + 1][lrow] = bv.y;
        Bs[lk4 + 2][lrow] = bv.z; Bs[lk4 + 3][lrow] = bv.w;
        __syncthreads();
#pragma unroll
        for (int kk = 0; kk < 8; kk++) {
            float4 a0 = *(const float4*)&As[kk][ty * 8];
            float4 a1 = *(const float4*)&As[kk][ty * 8 + 4];
            float4 b0 = *(const float4*)&Bs[kk][tx * 8];
            float4 b1 = *(const float4*)&Bs[kk][tx * 8 + 4];
            float a[8] = {a0.x, a0.y, a0.z, a0.w, a1.x, a1.y, a1.z, a1.w};
            float b[8] = {b0.x, b0.y, b0.z, b0.w, b1.x, b1.y, b1.z, b1.w};
#pragma unroll
            for (int j = 0; j < 8; j++)
#pragma unroll
                for (int i = 0; i < 8; i++) acc[j][i] += a[j] * b[i];
        }
    }

#pragma unroll
    for (int j = 0; j < 8; j++) {
        size_t row = (size_t)(m0 + ty * 8 + j);
        float* crow = C + row * N + n0 + tx * 8;
        float4 v0 = make_float4(acc[j][0], acc[j][1], acc[j][2], acc[j][3]);
        float4 v1 = make_float4(acc[j][4], acc[j][5], acc[j][6], acc[j][7]);
        if (res) {
            const float* rrow = res + row * N + n0 + tx * 8;
            float4 r0v = *(const float4*)(rrow);
            float4 r1v = *(const float4*)(rrow + 4);
            v0.x += r0v.x; v0.y += r0v.y; v0.z += r0v.z; v0.w += r0v.w;
            v1.x += r1v.x; v1.y += r1v.y; v1.z += r1v.z; v1.w += r1v.w;
        }
        *(float4*)(crow) = v0;
        *(float4*)(crow + 4) = v1;
    }
}

// ---------------------------------------------------------------------------
// Tensor-core flash attention (tf32 mma.sync m16n8k8).
// Block: 128 q-rows for one (b,h). 8 warps; warp w owns rows 16w..16w+15.
// K/V tiles 64x64, stored as pre-converted tf32 bits in smem, stride 68
// (conflict-free for both B-fragment patterns). Online softmax on the
// mma accumulator layout; P->A-fragment via intra-quad shuffles.
// ---------------------------------------------------------------------------
#define ATT_BQ 128
#define ATT_KT 64
#define KV_STRIDE 68

__global__ void __launch_bounds__(256) attn_tc(
    const float* __restrict__ qkv, float* __restrict__ ctx) {
    __shared__ uint32_t Ks[ATT_KT][KV_STRIDE];
    __shared__ uint32_t Vs[ATT_KT][KV_STRIDE];

    int qt = blockIdx.x;
    int bh = blockIdx.y;
    int b = bh >> 4, h = bh & 15;
    int tid = threadIdx.x, warp = tid >> 5, lane = tid & 31;
    int r = lane >> 2, s = lane & 3;
    int qr = warp * 16 + r;   // first of this thread's two Q rows (other = +8)

    // Q A-fragments (held for the whole K loop), scaled by HD^-0.5
    uint32_t qa[8][4];
    {
        const float* q0 = qkv + ((size_t)(qt * ATT_BQ + qr) * B_DIM + b) * E3_DIM + h * 64 + s;
        const float* q8 = q0 + (size_t)8 * B_DIM * E3_DIM;
#pragma unroll
        for (int kc = 0; kc < 8; kc++) {
            qa[kc][0] = f2tf(q0[kc * 8] * 0.125f);
            qa[kc][1] = f2tf(q8[kc * 8] * 0.125f);
            qa[kc][2] = f2tf(q0[kc * 8 + 4] * 0.125f);
            qa[kc][3] = f2tf(q8[kc * 8 + 4] * 0.125f);
        }
    }

    float m0v = -1e30f, m1v = -1e30f, l0 = 0.f, l1 = 0.f;
    float o[8][4];
#pragma unroll
    for (int nt = 0; nt < 8; nt++)
#pragma unroll
        for (int i = 0; i < 4; i++) o[nt][i] = 0.f;

    for (int kt = 0; kt < T_DIM / ATT_KT; kt++) {
        __syncthreads();
        for (int i = tid; i < ATT_KT * 64; i += 256) {
            int row = i >> 6, d = i & 63;
            size_t g = ((size_t)(kt * ATT_KT + row) * B_DIM + b) * E3_DIM + E_DIM + h * 64 + d;
            Ks[row][d] = f2tf(qkv[g]);
            Vs[row][d] = f2tf(qkv[g + E_DIM]);
        }
        __syncthreads();

        // S = Q K^T : 8 n-tiles (kv) x 8 k-chunks (hd)
        float sc[8][4];
#pragma unroll
        for (int nt = 0; nt < 8; nt++) {
            sc[nt][0] = sc[nt][1] = sc[nt][2] = sc[nt][3] = 0.f;
#pragma unroll
            for (int kc = 0; kc < 8; kc++) {
                uint32_t b0 = Ks[nt * 8 + r][kc * 8 + s];
                uint32_t b1 = Ks[nt * 8 + r][kc * 8 + s + 4];
                mma_tf32(sc[nt], qa[kc], b0, b1);
            }
        }

        // Online softmax on accumulator layout: rows (qr, qr+8), cols 2s,2s+1 (+8nt)
        float mx0 = -1e30f, mx1 = -1e30f;
#pragma unroll
        for (int nt = 0; nt < 8; nt++) {
            mx0 = fmaxf(mx0, fmaxf(sc[nt][0], sc[nt][1]));
            mx1 = fmaxf(mx1, fmaxf(sc[nt][2], sc[nt][3]));
        }
#pragma unroll
        for (int off = 1; off <= 2; off <<= 1) {
            mx0 = fmaxf(mx0, __shfl_xor_sync(0xffffffffu, mx0, off));
            mx1 = fmaxf(mx1, __shfl_xor_sync(0xffffffffu, mx1, off));
        }
        float mn0 = fmaxf(m0v, mx0), mn1 = fmaxf(m1v, mx1);
        float sc0 = __expf(m0v - mn0), sc1 = __expf(m1v - mn1);
        m0v = mn0; m1v = mn1;

        float rs0 = 0.f, rs1 = 0.f;
#pragma unroll
        for (int nt = 0; nt < 8; nt++) {
            sc[nt][0] = __expf(sc[nt][0] - mn0);
            sc[nt][1] = __expf(sc[nt][1] - mn0);
            sc[nt][2] = __expf(sc[nt][2] - mn1);
            sc[nt][3] = __expf(sc[nt][3] - mn1);
            rs0 += sc[nt][0] + sc[nt][1];
            rs1 += sc[nt][2] + sc[nt][3];
        }
#pragma unroll
        for (int off = 1; off <= 2; off <<= 1) {
            rs0 += __shfl_xor_sync(0xffffffffu, rs0, off);
            rs1 += __shfl_xor_sync(0xffffffffu, rs1, off);
        }
        l0 = l0 * sc0 + rs0;
        l1 = l1 * sc1 + rs1;
#pragma unroll
        for (int nt = 0; nt < 8; nt++) {
            o[nt][0] *= sc0; o[nt][1] *= sc0;
            o[nt][2] *= sc1; o[nt][3] *= sc1;
        }

        // O += P @ V. P tile kc = sc[kc] rearranged acc->A frag via quad shuffles.
        int srcA = (lane & ~3) | (s >> 1);
        int srcB = srcA + 2;
        bool odd = (s & 1);
#pragma unroll
        for (int kc = 0; kc < 8; kc++) {
            float t0a = __shfl_sync(0xffffffffu, sc[kc][0], srcA);
            float t1a = __shfl_sync(0xffffffffu, sc[kc][1], srcA);
            float t2a = __shfl_sync(0xffffffffu, sc[kc][2], srcA);
            float t3a = __shfl_sync(0xffffffffu, sc[kc][3], srcA);
            float t0b = __shfl_sync(0xffffffffu, sc[kc][0], srcB);
            float t1b = __shfl_sync(0xffffffffu, sc[kc][1], srcB);
            float t2b = __shfl_sync(0xffffffffu, sc[kc][2], srcB);
            float t3b = __shfl_sync(0xffffffffu, sc[kc][3], srcB);
            uint32_t pa[4];
            pa[0] = f2tf(odd ? t1a : t0a);
            pa[1] = f2tf(odd ? t3a : t2a);
            pa[2] = f2tf(odd ? t1b : t0b);
            pa[3] = f2tf(odd ? t3b : t2b);
#pragma unroll
            for (int nt = 0; nt < 8; nt++) {
                uint32_t b0 = Vs[kc * 8 + s][nt * 8 + r];
                uint32_t b1 = Vs[kc * 8 + s + 4][nt * 8 + r];
                mma_tf32(o[nt], pa, b0, b1);
            }
        }
    }

    // Normalize and write ctx
    float i0 = 1.0f / l0, i1 = 1.0f / l1;
    float* p0 = ctx + ((size_t)(qt * ATT_BQ + qr) * B_DIM + b) * E_DIM + h * 64;
    float* p1 = ctx + ((size_t)(qt * ATT_BQ + qr + 8) * B_DIM + b) * E_DIM + h * 64;
#pragma unroll
    for (int nt = 0; nt < 8; nt++) {
        *(float2*)(p0 + nt * 8 + 2 * s) = make_float2(o[nt][0] * i0, o[nt][1] * i0);
        *(float2*)(p1 + nt * 8 + 2 * s) = make_float2(o[nt][2] * i1, o[nt][3] * i1);
    }
}

// ---------------------------------------------------------------------------
extern "C" void kernel_launch(void* const* d_in, const int* in_sizes, int n_in,
                              void* d_out, int out_size) {
    const float* query = (const float*)d_in[0];
    const float* gamma = (const float*)d_in[1];
    const float* beta  = (const float*)d_in[2];
    const float* w_in  = (const float*)d_in[3];
    const float* w_out = (const float*)d_in[4];
    float* out = (float*)d_out;

    float *ln_p, *qkv_p, *ctx_p;
    cudaGetSymbolAddress((void**)&ln_p, g_ln);
    cudaGetSymbolAddress((void**)&qkv_p, g_qkv);
    cudaGetSymbolAddress((void**)&ctx_p, g_ctx);

    // 1. LayerNorm
    ln_kernel<<<NROWS, 256>>>(query, gamma, beta, ln_p);

    // 2. QKV projection: [4096,1024] x [3072,1024]^T
    gemm_tn128<<<dim3(E3_DIM / 128, NROWS / 128), 256>>>(
        ln_p, w_in, qkv_p, nullptr, NROWS, E3_DIM, E_DIM);

    // 3. Attention (tf32 tensor cores)
    attn_tc<<<dim3(T_DIM / ATT_BQ, B_DIM * H_DIM), 256>>>(qkv_p, ctx_p);

    // 4. Output projection + residual
    gemm_tn128<<<dim3(E_DIM / 128, NROWS / 128), 256>>>(
        ctx_p, w_out, out, query, NROWS, E_DIM, E_DIM);
}

// round 5
// speedup vs baseline: 2.1550x; 1.7091x over previous
#include <cuda_runtime.h>
#include <cuda_bf16.h>
#include <cstddef>
#include <cstdint>

// Problem constants
#define T_DIM 2048
#define B_DIM 2
#define E_DIM 1024
#define H_DIM 16
#define HD_DIM 64
#define E3_DIM 3072
#define NROWS (T_DIM * B_DIM)   // 4096

// Scratch (device globals: allocation-free rule)
__device__ float g_ln[(size_t)NROWS * E_DIM];    // 16 MB
__device__ float g_qkv[(size_t)NROWS * E3_DIM];  // 48 MB
__device__ float g_ctx[(size_t)NROWS * E_DIM];   // 16 MB

// ---------------------------------------------------------------------------
// Helpers: tf32 convert + m16n8k8 tf32 mma
// ---------------------------------------------------------------------------
__device__ __forceinline__ uint32_t f2tf(float x) {
    uint32_t r;
    asm("cvt.rna.tf32.f32 %0, %1;" : "=r"(r) : "f"(x));
    return r;
}

__device__ __forceinline__ void mma_tf32(float* d, const uint32_t* a,
                                         uint32_t b0, uint32_t b1) {
    asm volatile(
        "mma.sync.aligned.m16n8k8.row.col.f32.tf32.tf32.f32 "
        "{%0,%1,%2,%3}, {%4,%5,%6,%7}, {%8,%9}, {%0,%1,%2,%3};"
        : "+f"(d[0]), "+f"(d[1]), "+f"(d[2]), "+f"(d[3])
        : "r"(a[0]), "r"(a[1]), "r"(a[2]), "r"(a[3]), "r"(b0), "r"(b1));
}

// Empty kernel: launch-order padding so ncu (-s 5 -c 1) captures attn_tc.
__global__ void nop_kernel() {}

// ---------------------------------------------------------------------------
// LayerNorm: one block per (t,b) row of 1024
// ---------------------------------------------------------------------------
__global__ void ln_kernel(const float* __restrict__ x,
                          const float* __restrict__ gamma,
                          const float* __restrict__ beta,
                          float* __restrict__ y) {
    __shared__ float red_s[8], red_q[8];
    int row = blockIdx.x;
    int t = threadIdx.x;
    const float4* xr = (const float4*)(x + (size_t)row * E_DIM);
    float4 v = xr[t];
    float s = v.x + v.y + v.z + v.w;
    float q = v.x * v.x + v.y * v.y + v.z * v.z + v.w * v.w;
#pragma unroll
    for (int o = 16; o; o >>= 1) {
        s += __shfl_xor_sync(0xffffffffu, s, o);
        q += __shfl_xor_sync(0xffffffffu, q, o);
    }
    if ((t & 31) == 0) { red_s[t >> 5] = s; red_q[t >> 5] = q; }
    __syncthreads();
    if (t < 32) {
        s = (t < 8) ? red_s[t] : 0.f;
        q = (t < 8) ? red_q[t] : 0.f;
#pragma unroll
        for (int o = 4; o; o >>= 1) {
            s += __shfl_xor_sync(0xffffffffu, s, o);
            q += __shfl_xor_sync(0xffffffffu, q, o);
        }
        if (t == 0) { red_s[0] = s; red_q[0] = q; }
    }
    __syncthreads();
    s = red_s[0]; q = red_q[0];
    float mean = s * (1.0f / E_DIM);
    float var = q * (1.0f / E_DIM) - mean * mean;
    float inv = rsqrtf(var + 1e-5f);
    float4 g = ((const float4*)gamma)[t];
    float4 bb = ((const float4*)beta)[t];
    float4 o4;
    o4.x = (v.x - mean) * inv * g.x + bb.x;
    o4.y = (v.y - mean) * inv * g.y + bb.y;
    o4.z = (v.z - mean) * inv * g.z + bb.z;
    o4.w = (v.w - mean) * inv * g.w + bb.w;
    ((float4*)(y + (size_t)row * E_DIM))[t] = o4;
}

// ---------------------------------------------------------------------------
// tf32 tensor-core GEMM: C[M,N] = A[M,K] * B[N,K]^T (+ residual).
// 128x128 tile, BK=16, 256 threads / 8 warps (2x4), warp tile 64x32,
// m16n8k8 mma. smem stride 20 floats: fragment loads conflict-free
// (banks 20r mod 32 = {0,20,8,28,16,4,24,12}, +s covers all 32).
// ---------------------------------------------------------------------------
#define GS 20   // smem row stride in floats

__global__ void __launch_bounds__(256) gemm_tf32(
    const float* __restrict__ A, const float* __restrict__ Bw,
    float* __restrict__ C, const float* __restrict__ res,
    int M, int N, int K) {
    __shared__ uint32_t As[128 * GS];
    __shared__ uint32_t Bs[128 * GS];

    int t = threadIdx.x;
    int warp = t >> 5, lane = t & 31;
    int r = lane >> 2, s = lane & 3;
    int wm = (warp >> 2) * 64;   // 0 or 64
    int wn = (warp & 3) * 32;    // 0,32,64,96
    int m0 = blockIdx.y * 128, n0 = blockIdx.x * 128;

    int frow = t >> 2;           // 0..63
    int fk = (t & 3) * 4;        // 0,4,8,12
    const float* Ag0 = A + (size_t)(m0 + frow) * K + fk;
    const float* Ag1 = Ag0 + (size_t)64 * K;
    const float* Bg0 = Bw + (size_t)(n0 + frow) * K + fk;
    const float* Bg1 = Bg0 + (size_t)64 * K;
    uint32_t* asw0 = As + frow * GS + fk;
    uint32_t* asw1 = As + (frow + 64) * GS + fk;
    uint32_t* bsw0 = Bs + frow * GS + fk;
    uint32_t* bsw1 = Bs + (frow + 64) * GS + fk;

    float acc[4][4][4];
#pragma unroll
    for (int mt = 0; mt < 4; mt++)
#pragma unroll
        for (int nt = 0; nt < 4; nt++)
#pragma unroll
            for (int i = 0; i < 4; i++) acc[mt][nt][i] = 0.f;

    for (int k0 = 0; k0 < K; k0 += 16) {
        float4 a0 = *(const float4*)(Ag0 + k0);
        float4 a1 = *(const float4*)(Ag1 + k0);
        float4 b0 = *(const float4*)(Bg0 + k0);
        float4 b1 = *(const float4*)(Bg1 + k0);
        __syncthreads();
        asw0[0] = f2tf(a0.x); asw0[1] = f2tf(a0.y); asw0[2] = f2tf(a0.z); asw0[3] = f2tf(a0.w);
        asw1[0] = f2tf(a1.x); asw1[1] = f2tf(a1.y); asw1[2] = f2tf(a1.z); asw1[3] = f2tf(a1.w);
        bsw0[0] = f2tf(b0.x); bsw0[1] = f2tf(b0.y); bsw0[2] = f2tf(b0.z); bsw0[3] = f2tf(b0.w);
        bsw1[0] = f2tf(b1.x); bsw1[1] = f2tf(b1.y); bsw1[2] = f2tf(b1.z); bsw1[3] = f2tf(b1.w);
        __syncthreads();

#pragma unroll
        for (int ks = 0; ks < 2; ks++) {
            int kc = ks * 8;
            uint32_t afr[4][4];
#pragma unroll
            for (int mt = 0; mt < 4; mt++) {
                const uint32_t* ap = As + (wm + mt * 16 + r) * GS + kc + s;
                afr[mt][0] = ap[0];
                afr[mt][1] = ap[8 * GS];
                afr[mt][2] = ap[4];
                afr[mt][3] = ap[8 * GS + 4];
            }
            uint32_t bfr[4][2];
#pragma unroll
            for (int nt = 0; nt < 4; nt++) {
                const uint32_t* bp = Bs + (wn + nt * 8 + r) * GS + kc + s;
                bfr[nt][0] = bp[0];
                bfr[nt][1] = bp[4];
            }
#pragma unroll
            for (int mt = 0; mt < 4; mt++)
#pragma unroll
                for (int nt = 0; nt < 4; nt++)
                    mma_tf32(acc[mt][nt], afr[mt], bfr[nt][0], bfr[nt][1]);
        }
    }

    // Epilogue: thread(r,s) owns C[m+r/{+8}][n+2s/{+1}] per (mt,nt)
#pragma unroll
    for (int mt = 0; mt < 4; mt++) {
#pragma unroll
        for (int row8 = 0; row8 < 2; row8++) {
            size_t row = (size_t)(m0 + wm + mt * 16 + row8 * 8 + r);
            float* cp = C + row * N + n0 + wn;
            const float* rp = res ? res + row * N + n0 + wn : nullptr;
#pragma unroll
            for (int nt = 0; nt < 4; nt++) {
                float v0 = acc[mt][nt][row8 * 2];
                float v1 = acc[mt][nt][row8 * 2 + 1];
                if (rp) {
                    float2 rv = *(const float2*)(rp + nt * 8 + 2 * s);
                    v0 += rv.x; v1 += rv.y;
                }
                *(float2*)(cp + nt * 8 + 2 * s) = make_float2(v0, v1);
            }
        }
    }
}

// ---------------------------------------------------------------------------
// Tensor-core flash attention (tf32 mma.sync m16n8k8). (unchanged from R4)
// ---------------------------------------------------------------------------
#define ATT_BQ 128
#define ATT_KT 64
#define KV_STRIDE 68

__global__ void __launch_bounds__(256) attn_tc(
    const float* __restrict__ qkv, float* __restrict__ ctx) {
    __shared__ uint32_t Ks[ATT_KT][KV_STRIDE];
    __shared__ uint32_t Vs[ATT_KT][KV_STRIDE];

    int qt = blockIdx.x;
    int bh = blockIdx.y;
    int b = bh >> 4, h = bh & 15;
    int tid = threadIdx.x, warp = tid >> 5, lane = tid & 31;
    int r = lane >> 2, s = lane & 3;
    int qr = warp * 16 + r;

    uint32_t qa[8][4];
    {
        const float* q0 = qkv + ((size_t)(qt * ATT_BQ + qr) * B_DIM + b) * E3_DIM + h * 64 + s;
        const float* q8 = q0 + (size_t)8 * B_DIM * E3_DIM;
#pragma unroll
        for (int kc = 0; kc < 8; kc++) {
            qa[kc][0] = f2tf(q0[kc * 8] * 0.125f);
            qa[kc][1] = f2tf(q8[kc * 8] * 0.125f);
            qa[kc][2] = f2tf(q0[kc * 8 + 4] * 0.125f);
            qa[kc][3] = f2tf(q8[kc * 8 + 4] * 0.125f);
        }
    }

    float m0v = -1e30f, m1v = -1e30f, l0 = 0.f, l1 = 0.f;
    float o[8][4];
#pragma unroll
    for (int nt = 0; nt < 8; nt++)
#pragma unroll
        for (int i = 0; i < 4; i++) o[nt][i] = 0.f;

    for (int kt = 0; kt < T_DIM / ATT_KT; kt++) {
        __syncthreads();
        for (int i = tid; i < ATT_KT * 64; i += 256) {
            int row = i >> 6, d = i & 63;
            size_t g = ((size_t)(kt * ATT_KT + row) * B_DIM + b) * E3_DIM + E_DIM + h * 64 + d;
            Ks[row][d] = f2tf(qkv[g]);
            Vs[row][d] = f2tf(qkv[g + E_DIM]);
        }
        __syncthreads();

        float sc[8][4];
#pragma unroll
        for (int nt = 0; nt < 8; nt++) {
            sc[nt][0] = sc[nt][1] = sc[nt][2] = sc[nt][3] = 0.f;
#pragma unroll
            for (int kc = 0; kc < 8; kc++) {
                uint32_t b0 = Ks[nt * 8 + r][kc * 8 + s];
                uint32_t b1 = Ks[nt * 8 + r][kc * 8 + s + 4];
                mma_tf32(sc[nt], qa[kc], b0, b1);
            }
        }

        float mx0 = -1e30f, mx1 = -1e30f;
#pragma unroll
        for (int nt = 0; nt < 8; nt++) {
            mx0 = fmaxf(mx0, fmaxf(sc[nt][0], sc[nt][1]));
            mx1 = fmaxf(mx1, fmaxf(sc[nt][2], sc[nt][3]));
        }
#pragma unroll
        for (int off = 1; off <= 2; off <<= 1) {
            mx0 = fmaxf(mx0, __shfl_xor_sync(0xffffffffu, mx0, off));
            mx1 = fmaxf(mx1, __shfl_xor_sync(0xffffffffu, mx1, off));
        }
        float mn0 = fmaxf(m0v, mx0), mn1 = fmaxf(m1v, mx1);
        float sc0 = __expf(m0v - mn0), sc1 = __expf(m1v - mn1);
        m0v = mn0; m1v = mn1;

        float rs0 = 0.f, rs1 = 0.f;
#pragma unroll
        for (int nt = 0; nt < 8; nt++) {
            sc[nt][0] = __expf(sc[nt][0] - mn0);
            sc[nt][1] = __expf(sc[nt][1] - mn0);
            sc[nt][2] = __expf(sc[nt][2] - mn1);
            sc[nt][3] = __expf(sc[nt][3] - mn1);
            rs0 += sc[nt][0] + sc[nt][1];
            rs1 += sc[nt][2] + sc[nt][3];
        }
#pragma unroll
        for (int off = 1; off <= 2; off <<= 1) {
            rs0 += __shfl_xor_sync(0xffffffffu, rs0, off);
            rs1 += __shfl_xor_sync(0xffffffffu, rs1, off);
        }
        l0 = l0 * sc0 + rs0;
        l1 = l1 * sc1 + rs1;
#pragma unroll
        for (int nt = 0; nt < 8; nt++) {
            o[nt][0] *= sc0; o[nt][1] *= sc0;
            o[nt][2] *= sc1; o[nt][3] *= sc1;
        }

        int srcA = (lane & ~3) | (s >> 1);
        int srcB = srcA + 2;
        bool odd = (s & 1);
#pragma unroll
        for (int kc = 0; kc < 8; kc++) {
            float t0a = __shfl_sync(0xffffffffu, sc[kc][0], srcA);
            float t1a = __shfl_sync(0xffffffffu, sc[kc][1], srcA);
            float t2a = __shfl_sync(0xffffffffu, sc[kc][2], srcA);
            float t3a = __shfl_sync(0xffffffffu, sc[kc][3], srcA);
            float t0b = __shfl_sync(0xffffffffu, sc[kc][0], srcB);
            float t1b = __shfl_sync(0xffffffffu, sc[kc][1], srcB);
            float t2b = __shfl_sync(0xffffffffu, sc[kc][2], srcB);
            float t3b = __shfl_sync(0xffffffffu, sc[kc][3], srcB);
            uint32_t pa[4];
            pa[0] = f2tf(odd ? t1a : t0a);
            pa[1] = f2tf(odd ? t3a : t2a);
            pa[2] = f2tf(odd ? t1b : t0b);
            pa[3] = f2tf(odd ? t3b : t2b);
#pragma unroll
            for (int nt = 0; nt < 8; nt++) {
                uint32_t b0 = Vs[kc * 8 + s][nt * 8 + r];
                uint32_t b1 = Vs[kc * 8 + s + 4][nt * 8 + r];
                mma_tf32(o[nt], pa, b0, b1);
            }
        }
    }

    float i0 = 1.0f / l0, i1 = 1.0f / l1;
    float* p0 = ctx + ((size_t)(qt * ATT_BQ + qr) * B_DIM + b) * E_DIM + h * 64;
    float* p1 = ctx + ((size_t)(qt * ATT_BQ + qr + 8) * B_DIM + b) * E_DIM + h * 64;
#pragma unroll
    for (int nt = 0; nt < 8; nt++) {
        *(float2*)(p0 + nt * 8 + 2 * s) = make_float2(o[nt][0] * i0, o[nt][1] * i0);
        *(float2*)(p1 + nt * 8 + 2 * s) = make_float2(o[nt][2] * i1, o[nt][3] * i1);
    }
}

// ---------------------------------------------------------------------------
extern "C" void kernel_launch(void* const* d_in, const int* in_sizes, int n_in,
                              void* d_out, int out_size) {
    const float* query = (const float*)d_in[0];
    const float* gamma = (const float*)d_in[1];
    const float* beta  = (const float*)d_in[2];
    const float* w_in  = (const float*)d_in[3];
    const float* w_out = (const float*)d_in[4];
    float* out = (float*)d_out;

    float *ln_p, *qkv_p, *ctx_p;
    cudaGetSymbolAddress((void**)&ln_p, g_ln);
    cudaGetSymbolAddress((void**)&qkv_p, g_qkv);
    cudaGetSymbolAddress((void**)&ctx_p, g_ctx);

    // 1. LayerNorm                                   (launch #1)
    ln_kernel<<<NROWS, 256>>>(query, gamma, beta, ln_p);

    // 2. QKV projection (tf32 tensor cores)          (launch #2)
    gemm_tf32<<<dim3(E3_DIM / 128, NROWS / 128), 256>>>(
        ln_p, w_in, qkv_p, nullptr, NROWS, E3_DIM, E_DIM);

    // Padding so attn_tc is launch #6 (ncu -s 5 -c 1 captures it)
    nop_kernel<<<1, 32>>>();                       // #3
    nop_kernel<<<1, 32>>>();                       // #4
    nop_kernel<<<1, 32>>>();                       // #5

    // 3. Attention (tf32 tensor cores)               (launch #6)
    attn_tc<<<dim3(T_DIM / ATT_BQ, B_DIM * H_DIM), 256>>>(qkv_p, ctx_p);

    // 4. Output projection + residual (tf32)         (launch #7)
    gemm_tf32<<<dim3(E_DIM / 128, NROWS / 128), 256>>>(
        ctx_p, w_out, out, query, NROWS, E_DIM, E_DIM);
}